// round 4
// baseline (speedup 1.0000x reference)
#include <cuda_runtime.h>
#include <cstdint>

namespace {
constexpr int B = 16;
constexpr int L = 1024;
constexpr int H = 512;
constexpr int V = 32000;
constexpr int HALF = 256;
constexpr int TOK = B * L;           // 16384
constexpr float ALPHA_C = 0.05f;     // 1 - 0.95
constexpr float EPS_LN_C = 1e-5f;
constexpr float EPS_NORM_C = 1e-12f;
}

// ---------------- scratch (static device globals; no allocation) ----------------
__device__ float g_h0[TOK * H];            // embed gather output
__device__ float g_ff1[TOK * 2 * H];       // FFN hidden
__device__ float g_y2[TOK * H];            // FFN output (pre-LN)
__device__ float g_h[TOK * H];             // post-LN hidden
__device__ float g_kn[2 * L * B * HALF];   // normalized keys, layout [m][l][b][i]
__device__ float g_nrm[2 * L * B];         // clamped norms, layout [m][l][b]
__device__ float g_c[B * H];               // context  [b][m*HALF+i]
__device__ float g_r[B * H];               // readout projection

// ---------------- tensor-core helpers ----------------
__device__ __forceinline__ uint32_t to_tf32(float f) {
    uint32_t r;
    asm("cvt.rna.tf32.f32 %0, %1;" : "=r"(r) : "f"(f));
    return r;
}
__device__ __forceinline__ uint32_t smem_u32(const void* p) {
    return (uint32_t)__cvta_generic_to_shared(p);
}
__device__ __forceinline__ void ldsm_x4(uint32_t& r0, uint32_t& r1, uint32_t& r2,
                                        uint32_t& r3, uint32_t a) {
    asm volatile("ldmatrix.sync.aligned.m8n8.x4.shared.b16 {%0,%1,%2,%3}, [%4];"
                 : "=r"(r0), "=r"(r1), "=r"(r2), "=r"(r3) : "r"(a));
}
__device__ __forceinline__ void ldsm_x2(uint32_t& r0, uint32_t& r1, uint32_t a) {
    asm volatile("ldmatrix.sync.aligned.m8n8.x2.shared.b16 {%0,%1}, [%2];"
                 : "=r"(r0), "=r"(r1) : "r"(a));
}
__device__ __forceinline__ void mma_tf32(float* d, const uint32_t* a, const uint32_t* b) {
    asm volatile(
        "mma.sync.aligned.m16n8k8.row.col.f32.tf32.tf32.f32 "
        "{%0,%1,%2,%3},{%4,%5,%6,%7},{%8,%9},{%0,%1,%2,%3};"
        : "+f"(d[0]), "+f"(d[1]), "+f"(d[2]), "+f"(d[3])
        : "r"(a[0]), "r"(a[1]), "r"(a[2]), "r"(a[3]), "r"(b[0]), "r"(b[1]));
}

// ---------------- embedding gather ----------------
__global__ void k_gather(const int* __restrict__ seq, const float* __restrict__ embed,
                         float* __restrict__ out) {
    int t = blockIdx.x;
    int v = seq[t];
    const float4* src = reinterpret_cast<const float4*>(embed + (size_t)v * H);
    float4* dst = reinterpret_cast<float4*>(out + (size_t)t * H);
    dst[threadIdx.x] = src[threadIdx.x];
}

// ---------------- TF32 tensor GEMM: C[m,n] = A[m,:] . W[n,:] ----------------
// 128(M) x 64(N) CTA tile, BK=16, double-buffered smem, 8 warps in 4x2 grid,
// 32x32 warp tile -> 32 accumulator regs/thread, no spills at <=85 regs.
// MODE 0: +bias; MODE 1: +bias, relu; MODE 2: no bias, scatter to [l][b][n]
constexpr int SSTR = 20;   // smem row stride in words (16 + 4 pad)

template <int MODE>
__global__ void __launch_bounds__(256, 3) k_gemm(const float* __restrict__ A,
                                                 const float* __restrict__ W,
                                                 const float* __restrict__ bias,
                                                 float* __restrict__ C,
                                                 int N, int K) {
    __shared__ uint32_t As[2][128 * SSTR];   // 10 KB each
    __shared__ uint32_t Ws[2][64 * SSTR];    // 5 KB each  (total 30 KB)

    const int tid = threadIdx.x;
    const int bm = blockIdx.y * 128;
    const int bn = blockIdx.x * 64;
    const int warp = tid >> 5, lane = tid & 31;
    const int wm = warp & 3, wn = warp >> 2;   // 4 x 2 warp grid
    const int g = lane >> 2, tg = lane & 3;

    // ldmatrix source lanes
    const int a_r = lane & 15;                 // row within m16 tile
    const int a_c = (lane >> 4) << 2;          // k col offset 0/4
    const int b_r = lane & 7;                  // row within n8 tile
    const int b_c = ((lane >> 3) & 1) << 2;    // k col offset 0/4

    // global loaders: A = 128 rows x 16k (8 floats/thr), W = 64 rows x 16k (4 floats/thr)
    const int lrow = tid >> 1;
    const int lk = (tid & 1) * 8;
    const int wrow = tid >> 2;
    const int wk = (tid & 3) * 4;
    const float* Ap = A + (size_t)(bm + lrow) * K + lk;
    const float* Wp = W + (size_t)(bn + wrow) * K + wk;

    float acc[2][4][4];
#pragma unroll
    for (int mi = 0; mi < 2; ++mi)
#pragma unroll
        for (int ni = 0; ni < 4; ++ni)
#pragma unroll
            for (int q = 0; q < 4; ++q) acc[mi][ni][q] = 0.f;

    uint32_t ar[8], wr[4];
    auto load_global = [&](int pass) {
        float4 x = __ldg(reinterpret_cast<const float4*>(Ap + pass * 16));
        float4 y = __ldg(reinterpret_cast<const float4*>(Ap + pass * 16 + 4));
        float4 u = __ldg(reinterpret_cast<const float4*>(Wp + pass * 16));
        ar[0] = to_tf32(x.x); ar[1] = to_tf32(x.y); ar[2] = to_tf32(x.z); ar[3] = to_tf32(x.w);
        ar[4] = to_tf32(y.x); ar[5] = to_tf32(y.y); ar[6] = to_tf32(y.z); ar[7] = to_tf32(y.w);
        wr[0] = to_tf32(u.x); wr[1] = to_tf32(u.y); wr[2] = to_tf32(u.z); wr[3] = to_tf32(u.w);
    };
    auto store_smem = [&](int buf) {
        uint4* da = reinterpret_cast<uint4*>(&As[buf][lrow * SSTR + lk]);
        da[0] = make_uint4(ar[0], ar[1], ar[2], ar[3]);
        da[1] = make_uint4(ar[4], ar[5], ar[6], ar[7]);
        *reinterpret_cast<uint4*>(&Ws[buf][wrow * SSTR + wk]) =
            make_uint4(wr[0], wr[1], wr[2], wr[3]);
    };
    auto mma_pass = [&](int buf) {
#pragma unroll
        for (int ak = 0; ak < 2; ++ak) {
            int k0 = ak * 8;
            uint32_t afrag[2][4];
#pragma unroll
            for (int mi = 0; mi < 2; ++mi) {
                uint32_t addr = smem_u32(&As[buf][(wm * 32 + mi * 16 + a_r) * SSTR + k0 + a_c]);
                ldsm_x4(afrag[mi][0], afrag[mi][1], afrag[mi][2], afrag[mi][3], addr);
            }
            uint32_t bfrag[4][2];
#pragma unroll
            for (int ni = 0; ni < 4; ++ni) {
                uint32_t addr = smem_u32(&Ws[buf][(wn * 32 + ni * 8 + b_r) * SSTR + k0 + b_c]);
                ldsm_x2(bfrag[ni][0], bfrag[ni][1], addr);
            }
#pragma unroll
            for (int mi = 0; mi < 2; ++mi)
#pragma unroll
                for (int ni = 0; ni < 4; ++ni)
                    mma_tf32(acc[mi][ni], afrag[mi], bfrag[ni]);
        }
    };

    const int NPASS = K / 16;
    load_global(0);
    store_smem(0);
    __syncthreads();
    for (int p = 1; p < NPASS; ++p) {
        load_global(p);
        mma_pass((p - 1) & 1);
        store_smem(p & 1);
        __syncthreads();
    }
    mma_pass((NPASS - 1) & 1);

    // epilogue: acc reg q -> row g + (q>=2)*8, col tg*2 + (q&1)
#pragma unroll
    for (int mi = 0; mi < 2; ++mi) {
#pragma unroll
        for (int half = 0; half < 2; ++half) {
            int r = bm + wm * 32 + mi * 16 + g + half * 8;
#pragma unroll
            for (int ni = 0; ni < 4; ++ni) {
                int col = bn + wn * 32 + ni * 8 + tg * 2;
                float x = acc[mi][ni][half * 2 + 0];
                float y = acc[mi][ni][half * 2 + 1];
                if (MODE == 2) {
                    int b_ = r >> 10, l_ = r & 1023;
                    float* dst = C + ((size_t)l_ * B + b_) * HALF + col;
                    *reinterpret_cast<float2*>(dst) = make_float2(x, y);
                } else {
                    x += bias[col];
                    y += bias[col + 1];
                    if (MODE == 1) { x = fmaxf(x, 0.f); y = fmaxf(y, 0.f); }
                    float* dst = C + (size_t)r * N + col;
                    *reinterpret_cast<float2*>(dst) = make_float2(x, y);
                }
            }
        }
    }
}

// ---------------- residual + LayerNorm (warp per row) ----------------
__global__ void k_ln(const float* __restrict__ y2, const float* __restrict__ h0,
                     const float* __restrict__ gamma, const float* __restrict__ beta,
                     float* __restrict__ out) {
    int warp = threadIdx.x >> 5, lane = threadIdx.x & 31;
    int row = blockIdx.x * 8 + warp;
    const float4* a = reinterpret_cast<const float4*>(y2 + (size_t)row * H);
    const float4* hb = reinterpret_cast<const float4*>(h0 + (size_t)row * H);
    float x[16];
    float s = 0.f, s2 = 0.f;
#pragma unroll
    for (int i = 0; i < 4; ++i) {
        float4 u = a[lane + i * 32];
        float4 v = hb[lane + i * 32];
        float t0 = u.x + v.x, t1 = u.y + v.y, t2 = u.z + v.z, t3 = u.w + v.w;
        x[i * 4 + 0] = t0; x[i * 4 + 1] = t1; x[i * 4 + 2] = t2; x[i * 4 + 3] = t3;
        s += t0 + t1 + t2 + t3;
        s2 += t0 * t0 + t1 * t1 + t2 * t2 + t3 * t3;
    }
#pragma unroll
    for (int off = 16; off > 0; off >>= 1) {
        s += __shfl_xor_sync(0xffffffffu, s, off);
        s2 += __shfl_xor_sync(0xffffffffu, s2, off);
    }
    float mu = s * (1.f / H);
    float var = s2 * (1.f / H) - mu * mu;
    float rstd = rsqrtf(var + EPS_LN_C);
    float4* o = reinterpret_cast<float4*>(out + (size_t)row * H);
    const float4* g4 = reinterpret_cast<const float4*>(gamma);
    const float4* b4 = reinterpret_cast<const float4*>(beta);
#pragma unroll
    for (int i = 0; i < 4; ++i) {
        float4 gg = __ldg(g4 + lane + i * 32);
        float4 bb = __ldg(b4 + lane + i * 32);
        float4 r;
        r.x = (x[i * 4 + 0] - mu) * rstd * gg.x + bb.x;
        r.y = (x[i * 4 + 1] - mu) * rstd * gg.y + bb.y;
        r.z = (x[i * 4 + 2] - mu) * rstd * gg.z + bb.z;
        r.w = (x[i * 4 + 3] - mu) * rstd * gg.w + bb.w;
        o[lane + i * 32] = r;
    }
}

// ---------------- L2-normalize key rows in place, save clamped norm ----------------
__global__ void k_norm(float* __restrict__ kn, float* __restrict__ nrm) {
    int warp = threadIdx.x >> 5, lane = threadIdx.x & 31;
    int row = blockIdx.x * 8 + warp;               // 0 .. 2*L*B-1
    float4* p4 = reinterpret_cast<float4*>(kn + (size_t)row * HALF);
    float4 v0 = p4[lane];
    float4 v1 = p4[lane + 32];
    float s = v0.x * v0.x + v0.y * v0.y + v0.z * v0.z + v0.w * v0.w
            + v1.x * v1.x + v1.y * v1.y + v1.z * v1.z + v1.w * v1.w;
#pragma unroll
    for (int off = 16; off > 0; off >>= 1) s += __shfl_xor_sync(0xffffffffu, s, off);
    float n = sqrtf(s);
    float nc = fmaxf(n, EPS_NORM_C);
    float inv = 1.f / nc;
    v0.x *= inv; v0.y *= inv; v0.z *= inv; v0.w *= inv;
    v1.x *= inv; v1.y *= inv; v1.z *= inv; v1.w *= inv;
    p4[lane] = v0;
    p4[lane + 32] = v1;
    if (lane == 0) nrm[row] = nc;
}

// ---------------- EMA scan, backward-query form ----------------
__device__ __forceinline__ void scan_load4(const float* kn, const float* nr, int t0,
                                           int lane, float k4[4][8], float n4[4]) {
    const int STRD = B * HALF;
#pragma unroll
    for (int j = 0; j < 4; ++j) {
        const float4* p = reinterpret_cast<const float4*>(kn + (size_t)(t0 + j) * STRD + lane * 8);
        float4 u = __ldg(p), w = __ldg(p + 1);
        k4[j][0] = u.x; k4[j][1] = u.y; k4[j][2] = u.z; k4[j][3] = u.w;
        k4[j][4] = w.x; k4[j][5] = w.y; k4[j][6] = w.z; k4[j][7] = w.w;
        n4[j] = __ldg(nr + (size_t)(t0 + j) * B);
    }
}

__global__ void __launch_bounds__(32) k_scan(const float* __restrict__ kn_all,
                                             const float* __restrict__ nrm_all,
                                             float* __restrict__ cbuf) {
    const int lane = threadIdx.x;
    const int m = blockIdx.x >> 4;
    const int b = blockIdx.x & 15;
    const float* kn = kn_all + (size_t)m * L * B * HALF + b * HALF;
    const float* nr = nrm_all + (size_t)m * L * B + b;
    const int STRD = B * HALF;

    float v[8], cac[8];
    {
        const float4* p = reinterpret_cast<const float4*>(kn + (size_t)(L - 1) * STRD + lane * 8);
        float4 u = __ldg(p), w = __ldg(p + 1);
        float qn = __ldg(nr + (size_t)(L - 1) * B);
        v[0] = u.x * qn; v[1] = u.y * qn; v[2] = u.z * qn; v[3] = u.w * qn;
        v[4] = w.x * qn; v[5] = w.y * qn; v[6] = w.z * qn; v[7] = w.w * qn;
    }
#pragma unroll
    for (int j = 0; j < 8; ++j) cac[j] = 0.f;

    float cur[4][8], nxt[4][8], curn[4], nxtn[4];
    scan_load4(kn, nr, L - 5, lane, cur, curn);     // first block: t = L-5..L-2

    for (int t0 = L - 5; t0 >= 3; t0 -= 4) {
        bool more = (t0 > 3);
        if (more) scan_load4(kn, nr, t0 - 4, lane, nxt, nxtn);

        float red[10];
#pragma unroll
        for (int q = 0; q < 10; ++q) red[q] = 0.f;
#pragma unroll
        for (int j = 0; j < 8; ++j) {
            float vj = v[j];
            float k0 = cur[0][j], k1 = cur[1][j], k2 = cur[2][j], k3 = cur[3][j];
            red[0] += k0 * vj;
            red[1] += k1 * vj;
            red[2] += k2 * vj;
            red[3] += k3 * vj;
            red[4] += k3 * k2;
            red[5] += k3 * k1;
            red[6] += k3 * k0;
            red[7] += k2 * k1;
            red[8] += k2 * k0;
            red[9] += k1 * k0;
        }
#pragma unroll
        for (int off = 16; off > 0; off >>= 1)
#pragma unroll
            for (int q = 0; q < 10; ++q)
                red[q] += __shfl_xor_sync(0xffffffffu, red[q], off);

        float s3 = red[3];
        float s2 = red[2] - ALPHA_C * red[4] * s3;
        float s1 = red[1] - ALPHA_C * (red[5] * s3 + red[7] * s2);
        float s0 = red[0] - ALPHA_C * (red[6] * s3 + red[8] * s2 + red[9] * s1);
        float w3 = curn[3] * s3, w2 = curn[2] * s2, w1 = curn[1] * s1, w0 = curn[0] * s0;
#pragma unroll
        for (int j = 0; j < 8; ++j) {
            float k0 = cur[0][j], k1 = cur[1][j], k2 = cur[2][j], k3 = cur[3][j];
            v[j] -= ALPHA_C * (k3 * s3 + k2 * s2 + k1 * s1 + k0 * s0);
            cac[j] += k3 * w3 + k2 * w2 + k1 * w1 + k0 * w0;
        }
        if (more) {
#pragma unroll
            for (int j = 0; j < 4; ++j) {
                curn[j] = nxtn[j];
#pragma unroll
                for (int q = 0; q < 8; ++q) cur[j][q] = nxt[j][q];
            }
        }
    }

    for (int t = 2; t >= 0; --t) {
        float kt[8];
        const float4* p = reinterpret_cast<const float4*>(kn + (size_t)t * STRD + lane * 8);
        float4 u = __ldg(p), w = __ldg(p + 1);
        kt[0] = u.x; kt[1] = u.y; kt[2] = u.z; kt[3] = u.w;
        kt[4] = w.x; kt[5] = w.y; kt[6] = w.z; kt[7] = w.w;
        float nt = __ldg(nr + (size_t)t * B);
        float s = 0.f;
#pragma unroll
        for (int j = 0; j < 8; ++j) s += kt[j] * v[j];
#pragma unroll
        for (int off = 16; off > 0; off >>= 1) s += __shfl_xor_sync(0xffffffffu, s, off);
        float ws = nt * s;
#pragma unroll
        for (int j = 0; j < 8; ++j) {
            cac[j] += kt[j] * ws;
            v[j] -= ALPHA_C * s * kt[j];
        }
    }

    float* out = cbuf + b * H + m * HALF + lane * 8;
#pragma unroll
    for (int j = 0; j < 8; ++j) out[j] = ALPHA_C * cac[j];
}

// ---------------- r = c @ rp_w^T + rp_b ----------------
__global__ void k_rp(const float* __restrict__ c, const float* __restrict__ W,
                     const float* __restrict__ bias, float* __restrict__ r) {
    __shared__ float cs[B * (H + 1)];
    for (int i = threadIdx.x; i < B * H; i += 256) {
        int bb = i >> 9, hh = i & 511;
        cs[bb * (H + 1) + hh] = c[i];
    }
    __syncthreads();
    int g = blockIdx.x * 16 + (threadIdx.x >> 4);
    int b = threadIdx.x & 15;
    const float* w = W + (size_t)g * H;
    const float* cb = &cs[b * (H + 1)];
    float acc = 0.f;
    for (int h = 0; h < H; h += 4) {
        float4 wv = __ldg(reinterpret_cast<const float4*>(w + h));
        acc += cb[h] * wv.x + cb[h + 1] * wv.y + cb[h + 2] * wv.z + cb[h + 3] * wv.w;
    }
    r[b * H + g] = acc + bias[g];
}

// ---------------- out = r @ out_w^T + out_b ----------------
__global__ void k_out(const float* __restrict__ r, const float* __restrict__ W,
                      const float* __restrict__ bias, float* __restrict__ out) {
    __shared__ float rs[B * H];
    for (int i = threadIdx.x; i < B * H; i += 256) rs[i] = r[i];
    __syncthreads();
    int v = blockIdx.x * 256 + threadIdx.x;
    float acc[B];
#pragma unroll
    for (int b = 0; b < B; ++b) acc[b] = 0.f;
    const float4* w = reinterpret_cast<const float4*>(W + (size_t)v * H);
#pragma unroll 4
    for (int i = 0; i < H / 4; ++i) {
        float4 wv = __ldg(w + i);
#pragma unroll
        for (int b = 0; b < B; ++b) {
            float4 rv = *reinterpret_cast<const float4*>(&rs[b * H + i * 4]);
            acc[b] += rv.x * wv.x + rv.y * wv.y + rv.z * wv.z + rv.w * wv.w;
        }
    }
    float bb = __ldg(bias + v);
#pragma unroll
    for (int b = 0; b < B; ++b) out[(size_t)b * V + v] = acc[b] + bb;
}

// ---------------- launch ----------------
extern "C" void kernel_launch(void* const* d_in, const int* in_sizes, int n_in,
                              void* d_out, int out_size) {
    const int*   seq   = (const int*)d_in[0];
    const float* embed = (const float*)d_in[1];
    const float* ff_w1 = (const float*)d_in[2];
    const float* ff_b1 = (const float*)d_in[3];
    const float* ff_w2 = (const float*)d_in[4];
    const float* ff_b2 = (const float*)d_in[5];
    const float* gamma = (const float*)d_in[6];
    const float* beta  = (const float*)d_in[7];
    const float* sem_w = (const float*)d_in[8];
    const float* epi_w = (const float*)d_in[9];
    const float* rp_w  = (const float*)d_in[10];
    const float* rp_b  = (const float*)d_in[11];
    const float* out_w = (const float*)d_in[12];
    const float* out_b = (const float*)d_in[13];
    float* out = (float*)d_out;

    float *h0, *ff1, *y2, *h, *kn, *nrm, *c, *r;
    cudaGetSymbolAddress((void**)&h0,  g_h0);
    cudaGetSymbolAddress((void**)&ff1, g_ff1);
    cudaGetSymbolAddress((void**)&y2,  g_y2);
    cudaGetSymbolAddress((void**)&h,   g_h);
    cudaGetSymbolAddress((void**)&kn,  g_kn);
    cudaGetSymbolAddress((void**)&nrm, g_nrm);
    cudaGetSymbolAddress((void**)&c,   g_c);
    cudaGetSymbolAddress((void**)&r,   g_r);

    // 1. embedding gather
    k_gather<<<TOK, 128>>>(seq, embed, h0);
    // 2. FFN up (relu)   [16384 x 1024 x 512]
    k_gemm<1><<<dim3(2 * H / 64, TOK / 128), 256>>>(h0, ff_w1, ff_b1, ff1, 2 * H, H);
    // 3. FFN down        [16384 x 512 x 1024]
    k_gemm<0><<<dim3(H / 64, TOK / 128), 256>>>(ff1, ff_w2, ff_b2, y2, H, 2 * H);
    // 4. residual + layernorm
    k_ln<<<TOK / 8, 256>>>(y2, h0, gamma, beta, h);
    // 5+6. key projections, scattered to [l][b][c]
    k_gemm<2><<<dim3(HALF / 64, TOK / 128), 256>>>(h, sem_w, nullptr, kn, HALF, H);
    k_gemm<2><<<dim3(HALF / 64, TOK / 128), 256>>>(h, epi_w, nullptr,
                                                   kn + (size_t)L * B * HALF, HALF, H);
    // 7. normalize keys in place, stash clamped norms
    k_norm<<<(2 * L * B) / 8, 256>>>(kn, nrm);
    // 8. backward-query scan (O(L*HALF) per chain)
    k_scan<<<32, 32>>>(kn, nrm, c);
    // 9. readout projection
    k_rp<<<H / 16, 256>>>(c, rp_w, rp_b, r);
    // 10. logits
    k_out<<<V / 256, 256>>>(r, out_w, out_b, out);
}

// round 5
// speedup vs baseline: 1.3744x; 1.3744x over previous
#include <cuda_runtime.h>
#include <cstdint>

namespace {
constexpr int B = 16;
constexpr int L = 1024;
constexpr int H = 512;
constexpr int V = 32000;
constexpr int HALF = 256;
constexpr int TOK = B * L;           // 16384
constexpr float ALPHA_C = 0.05f;     // 1 - 0.95
constexpr float EPS_LN_C = 1e-5f;
constexpr float EPS_NORM_C = 1e-12f;
}

// ---------------- scratch (static device globals; no allocation) ----------------
__device__ float g_h0[TOK * H];            // embed gather output (tf32-rounded)
__device__ float g_ff1[TOK * 2 * H];       // FFN hidden (tf32-rounded)
__device__ float g_y2[TOK * H];            // FFN output (pre-LN)
__device__ float g_h[TOK * H];             // post-LN hidden (tf32-rounded)
__device__ float g_kn[2 * L * B * HALF];   // normalized keys, layout [m][l][b][i]
__device__ float g_nrm[2 * L * B];         // clamped norms, layout [m][l][b]
__device__ float g_c[B * H];               // context  [b][m*HALF+i]
__device__ float g_r[B * H];               // readout projection
__device__ float g_w1r[2 * H * H];         // tf32-rounded ff_w1
__device__ float g_w2r[2 * H * H];         // tf32-rounded ff_w2
__device__ float g_semr[HALF * H];         // tf32-rounded sem_w
__device__ float g_epir[HALF * H];         // tf32-rounded epi_w

// ---------------- helpers ----------------
__device__ __forceinline__ float rnd_tf32(float f) {
    uint32_t r;
    asm("cvt.rna.tf32.f32 %0, %1;" : "=r"(r) : "f"(f));
    return __uint_as_float(r);
}
__device__ __forceinline__ uint32_t smem_u32(const void* p) {
    return (uint32_t)__cvta_generic_to_shared(p);
}
__device__ __forceinline__ void cp16(uint32_t dst, const void* src) {
    asm volatile("cp.async.cg.shared.global [%0], [%1], 16;" :: "r"(dst), "l"(src));
}
__device__ __forceinline__ void ldsm_x4(uint32_t& r0, uint32_t& r1, uint32_t& r2,
                                        uint32_t& r3, uint32_t a) {
    asm volatile("ldmatrix.sync.aligned.m8n8.x4.shared.b16 {%0,%1,%2,%3}, [%4];"
                 : "=r"(r0), "=r"(r1), "=r"(r2), "=r"(r3) : "r"(a));
}
__device__ __forceinline__ void ldsm_x2(uint32_t& r0, uint32_t& r1, uint32_t a) {
    asm volatile("ldmatrix.sync.aligned.m8n8.x2.shared.b16 {%0,%1}, [%2];"
                 : "=r"(r0), "=r"(r1) : "r"(a));
}
__device__ __forceinline__ void mma_tf32(float* d, const uint32_t* a, const uint32_t* b) {
    asm volatile(
        "mma.sync.aligned.m16n8k8.row.col.f32.tf32.tf32.f32 "
        "{%0,%1,%2,%3},{%4,%5,%6,%7},{%8,%9},{%0,%1,%2,%3};"
        : "+f"(d[0]), "+f"(d[1]), "+f"(d[2]), "+f"(d[3])
        : "r"(a[0]), "r"(a[1]), "r"(a[2]), "r"(a[3]), "r"(b[0]), "r"(b[1]));
}

// ---------------- weight pre-rounding ----------------
__global__ void k_round(const float* __restrict__ src, float* __restrict__ dst) {
    int i = blockIdx.x * 256 + threadIdx.x;
    float4 v = __ldg(reinterpret_cast<const float4*>(src) + i);
    v.x = rnd_tf32(v.x); v.y = rnd_tf32(v.y);
    v.z = rnd_tf32(v.z); v.w = rnd_tf32(v.w);
    reinterpret_cast<float4*>(dst)[i] = v;
}

// ---------------- embedding gather (rounds to tf32) ----------------
__global__ void k_gather(const int* __restrict__ seq, const float* __restrict__ embed,
                         float* __restrict__ out) {
    int t = blockIdx.x;
    int v = seq[t];
    const float4* src = reinterpret_cast<const float4*>(embed + (size_t)v * H);
    float4* dst = reinterpret_cast<float4*>(out + (size_t)t * H);
    float4 x = src[threadIdx.x];
    x.x = rnd_tf32(x.x); x.y = rnd_tf32(x.y);
    x.z = rnd_tf32(x.z); x.w = rnd_tf32(x.w);
    dst[threadIdx.x] = x;
}

// ---------------- TF32 tensor GEMM: C[m,n] = A[m,:] . W[n,:] ----------------
// A and W are pre-rounded to tf32-representable fp32.
// 128x128 CTA tile, BK=16, 3-stage cp.async pipeline, swizzled smem (no pad),
// one __syncthreads per k-tile. 8 warps in 2(M) x 4(N) grid, 64x32 warp tiles.
// MODE 0: +bias; MODE 1: +bias+relu+round(feeds next GEMM); MODE 2: scatter [l][b][n]
__device__ __forceinline__ int sw_off(int row, int seg) {
    return row * 16 + (((seg ^ ((row >> 1) & 3))) << 2);
}

template <int MODE>
__global__ void __launch_bounds__(256, 2) k_gemm(const float* __restrict__ A,
                                                 const float* __restrict__ W,
                                                 const float* __restrict__ bias,
                                                 float* __restrict__ C,
                                                 int N, int K) {
    __shared__ uint32_t As[3][128 * 16];   // 8 KB / stage
    __shared__ uint32_t Ws[3][128 * 16];   // total 48 KB

    const int tid = threadIdx.x;
    const int bm = blockIdx.y * 128;
    const int bn = blockIdx.x * 128;
    const int warp = tid >> 5, lane = tid & 31;
    const int wm = warp >> 2, wn = warp & 3;   // 2 x 4 warp grid
    const int g = lane >> 2, tg = lane & 3;

    // global loader: thread -> (row lrow, segment pair lseg/lseg+1)
    const int lrow = tid >> 1;
    const int lseg = (tid & 1) * 2;
    const float* Ap = A + (size_t)(bm + lrow) * K + lseg * 4;
    const float* Wp = W + (size_t)(bn + lrow) * K + lseg * 4;
    const int d0 = sw_off(lrow, lseg);
    const int d1 = sw_off(lrow, lseg + 1);

    float acc[4][4][4];
#pragma unroll
    for (int mi = 0; mi < 4; ++mi)
#pragma unroll
        for (int ni = 0; ni < 4; ++ni)
#pragma unroll
            for (int q = 0; q < 4; ++q) acc[mi][ni][q] = 0.f;

    auto issue_tile = [&](int stage, int kt) {
        cp16(smem_u32(&As[stage][d0]), Ap + kt);
        cp16(smem_u32(&As[stage][d1]), Ap + kt + 4);
        cp16(smem_u32(&Ws[stage][d0]), Wp + kt);
        cp16(smem_u32(&Ws[stage][d1]), Wp + kt + 4);
        asm volatile("cp.async.commit_group;" ::: "memory");
    };

    auto mma_pass = [&](int buf) {
#pragma unroll
        for (int ak = 0; ak < 2; ++ak) {
            uint32_t afrag[4][4];
#pragma unroll
            for (int mi = 0; mi < 4; ++mi) {
                int row = wm * 64 + mi * 16 + (lane & 15);
                int seg = ak * 2 + (lane >> 4);
                ldsm_x4(afrag[mi][0], afrag[mi][1], afrag[mi][2], afrag[mi][3],
                        smem_u32(&As[buf][sw_off(row, seg)]));
            }
            uint32_t bfrag[4][2];
#pragma unroll
            for (int ni = 0; ni < 4; ++ni) {
                int row = wn * 32 + ni * 8 + (lane & 7);
                int seg = ak * 2 + ((lane >> 3) & 1);
                ldsm_x2(bfrag[ni][0], bfrag[ni][1],
                        smem_u32(&Ws[buf][sw_off(row, seg)]));
            }
#pragma unroll
            for (int mi = 0; mi < 4; ++mi)
#pragma unroll
                for (int ni = 0; ni < 4; ++ni)
                    mma_tf32(acc[mi][ni], afrag[mi], bfrag[ni]);
        }
    };

    const int NPASS = K / 16;
    issue_tile(0, 0);
    issue_tile(1, 16);

    int p = 0;
    for (; p < NPASS - 1; ++p) {
        asm volatile("cp.async.wait_group 1;" ::: "memory");
        __syncthreads();
        if (p + 2 < NPASS) issue_tile((p + 2) % 3, (p + 2) * 16);
        mma_pass(p % 3);
    }
    asm volatile("cp.async.wait_group 0;" ::: "memory");
    __syncthreads();
    mma_pass(p % 3);

    // epilogue: acc reg q -> row g + (q>=2)*8, col tg*2 + (q&1)
#pragma unroll
    for (int mi = 0; mi < 4; ++mi) {
#pragma unroll
        for (int half = 0; half < 2; ++half) {
            int r = bm + wm * 64 + mi * 16 + g + half * 8;
#pragma unroll
            for (int ni = 0; ni < 4; ++ni) {
                int col = bn + wn * 32 + ni * 8 + tg * 2;
                float x = acc[mi][ni][half * 2 + 0];
                float y = acc[mi][ni][half * 2 + 1];
                if (MODE == 2) {
                    int b_ = r >> 10, l_ = r & 1023;
                    float* dst = C + ((size_t)l_ * B + b_) * HALF + col;
                    *reinterpret_cast<float2*>(dst) = make_float2(x, y);
                } else {
                    x += bias[col];
                    y += bias[col + 1];
                    if (MODE == 1) {
                        x = rnd_tf32(fmaxf(x, 0.f));
                        y = rnd_tf32(fmaxf(y, 0.f));
                    }
                    float* dst = C + (size_t)r * N + col;
                    *reinterpret_cast<float2*>(dst) = make_float2(x, y);
                }
            }
        }
    }
}

// ---------------- residual + LayerNorm (warp per row; rounds output) ----------------
__global__ void k_ln(const float* __restrict__ y2, const float* __restrict__ h0,
                     const float* __restrict__ gamma, const float* __restrict__ beta,
                     float* __restrict__ out) {
    int warp = threadIdx.x >> 5, lane = threadIdx.x & 31;
    int row = blockIdx.x * 8 + warp;
    const float4* a = reinterpret_cast<const float4*>(y2 + (size_t)row * H);
    const float4* hb = reinterpret_cast<const float4*>(h0 + (size_t)row * H);
    float x[16];
    float s = 0.f, s2 = 0.f;
#pragma unroll
    for (int i = 0; i < 4; ++i) {
        float4 u = a[lane + i * 32];
        float4 v = hb[lane + i * 32];
        float t0 = u.x + v.x, t1 = u.y + v.y, t2 = u.z + v.z, t3 = u.w + v.w;
        x[i * 4 + 0] = t0; x[i * 4 + 1] = t1; x[i * 4 + 2] = t2; x[i * 4 + 3] = t3;
        s += t0 + t1 + t2 + t3;
        s2 += t0 * t0 + t1 * t1 + t2 * t2 + t3 * t3;
    }
#pragma unroll
    for (int off = 16; off > 0; off >>= 1) {
        s += __shfl_xor_sync(0xffffffffu, s, off);
        s2 += __shfl_xor_sync(0xffffffffu, s2, off);
    }
    float mu = s * (1.f / H);
    float var = s2 * (1.f / H) - mu * mu;
    float rstd = rsqrtf(var + EPS_LN_C);
    float4* o = reinterpret_cast<float4*>(out + (size_t)row * H);
    const float4* g4 = reinterpret_cast<const float4*>(gamma);
    const float4* b4 = reinterpret_cast<const float4*>(beta);
#pragma unroll
    for (int i = 0; i < 4; ++i) {
        float4 gg = __ldg(g4 + lane + i * 32);
        float4 bb = __ldg(b4 + lane + i * 32);
        float4 r;
        r.x = rnd_tf32((x[i * 4 + 0] - mu) * rstd * gg.x + bb.x);
        r.y = rnd_tf32((x[i * 4 + 1] - mu) * rstd * gg.y + bb.y);
        r.z = rnd_tf32((x[i * 4 + 2] - mu) * rstd * gg.z + bb.z);
        r.w = rnd_tf32((x[i * 4 + 3] - mu) * rstd * gg.w + bb.w);
        o[lane + i * 32] = r;
    }
}

// ---------------- L2-normalize key rows in place, save clamped norm ----------------
__global__ void k_norm(float* __restrict__ kn, float* __restrict__ nrm) {
    int warp = threadIdx.x >> 5, lane = threadIdx.x & 31;
    int row = blockIdx.x * 8 + warp;               // 0 .. 2*L*B-1
    float4* p4 = reinterpret_cast<float4*>(kn + (size_t)row * HALF);
    float4 v0 = p4[lane];
    float4 v1 = p4[lane + 32];
    float s = v0.x * v0.x + v0.y * v0.y + v0.z * v0.z + v0.w * v0.w
            + v1.x * v1.x + v1.y * v1.y + v1.z * v1.z + v1.w * v1.w;
#pragma unroll
    for (int off = 16; off > 0; off >>= 1) s += __shfl_xor_sync(0xffffffffu, s, off);
    float n = sqrtf(s);
    float nc = fmaxf(n, EPS_NORM_C);
    float inv = 1.f / nc;
    v0.x *= inv; v0.y *= inv; v0.z *= inv; v0.w *= inv;
    v1.x *= inv; v1.y *= inv; v1.z *= inv; v1.w *= inv;
    p4[lane] = v0;
    p4[lane + 32] = v1;
    if (lane == 0) nrm[row] = nc;
}

// ---------------- EMA scan, backward-query form, prefetch distance 2 ----------------
__device__ __forceinline__ void scan_load4(const float* kn, const float* nr, int t0,
                                           int lane, float k4[4][8], float n4[4]) {
    const int STRD = B * HALF;
#pragma unroll
    for (int j = 0; j < 4; ++j) {
        const float4* p = reinterpret_cast<const float4*>(kn + (size_t)(t0 + j) * STRD + lane * 8);
        float4 u = __ldg(p), w = __ldg(p + 1);
        k4[j][0] = u.x; k4[j][1] = u.y; k4[j][2] = u.z; k4[j][3] = u.w;
        k4[j][4] = w.x; k4[j][5] = w.y; k4[j][6] = w.z; k4[j][7] = w.w;
        n4[j] = __ldg(nr + (size_t)(t0 + j) * B);
    }
}

__device__ __forceinline__ void scan_step4(const float cur[4][8], const float curn[4],
                                           float v[8], float cac[8]) {
    float red[10];
#pragma unroll
    for (int q = 0; q < 10; ++q) red[q] = 0.f;
#pragma unroll
    for (int j = 0; j < 8; ++j) {
        float vj = v[j];
        float k0 = cur[0][j], k1 = cur[1][j], k2 = cur[2][j], k3 = cur[3][j];
        red[0] += k0 * vj;
        red[1] += k1 * vj;
        red[2] += k2 * vj;
        red[3] += k3 * vj;
        red[4] += k3 * k2;
        red[5] += k3 * k1;
        red[6] += k3 * k0;
        red[7] += k2 * k1;
        red[8] += k2 * k0;
        red[9] += k1 * k0;
    }
#pragma unroll
    for (int off = 16; off > 0; off >>= 1)
#pragma unroll
        for (int q = 0; q < 10; ++q)
            red[q] += __shfl_xor_sync(0xffffffffu, red[q], off);

    float s3 = red[3];
    float s2 = red[2] - ALPHA_C * red[4] * s3;
    float s1 = red[1] - ALPHA_C * (red[5] * s3 + red[7] * s2);
    float s0 = red[0] - ALPHA_C * (red[6] * s3 + red[8] * s2 + red[9] * s1);
    float w3 = curn[3] * s3, w2 = curn[2] * s2, w1 = curn[1] * s1, w0 = curn[0] * s0;
#pragma unroll
    for (int j = 0; j < 8; ++j) {
        float k0 = cur[0][j], k1 = cur[1][j], k2 = cur[2][j], k3 = cur[3][j];
        v[j] -= ALPHA_C * (k3 * s3 + k2 * s2 + k1 * s1 + k0 * s0);
        cac[j] += k3 * w3 + k2 * w2 + k1 * w1 + k0 * w0;
    }
}

__global__ void __launch_bounds__(32) k_scan(const float* __restrict__ kn_all,
                                             const float* __restrict__ nrm_all,
                                             float* __restrict__ cbuf) {
    const int lane = threadIdx.x;
    const int m = blockIdx.x >> 4;
    const int b = blockIdx.x & 15;
    const float* kn = kn_all + (size_t)m * L * B * HALF + b * HALF;
    const float* nr = nrm_all + (size_t)m * L * B + b;
    const int STRD = B * HALF;

    float v[8], cac[8];
    {
        const float4* p = reinterpret_cast<const float4*>(kn + (size_t)(L - 1) * STRD + lane * 8);
        float4 u = __ldg(p), w = __ldg(p + 1);
        float qn = __ldg(nr + (size_t)(L - 1) * B);
        v[0] = u.x * qn; v[1] = u.y * qn; v[2] = u.z * qn; v[3] = u.w * qn;
        v[4] = w.x * qn; v[5] = w.y * qn; v[6] = w.z * qn; v[7] = w.w * qn;
    }
#pragma unroll
    for (int j = 0; j < 8; ++j) cac[j] = 0.f;

    float bA[4][8], bB[4][8], bC[4][8], nA[4], nB[4], nC[4];
    scan_load4(kn, nr, L - 5, lane, bA, nA);    // t0 = 1019
    scan_load4(kn, nr, L - 9, lane, bB, nB);    // t0 = 1015

    int t0 = L - 5;
    for (int it = 0; it < 85; ++it) {
        if (t0 >= 11) scan_load4(kn, nr, t0 - 8, lane, bC, nC);
        scan_step4(bA, nA, v, cac);
        t0 -= 4;
        if (t0 >= 11) scan_load4(kn, nr, t0 - 8, lane, bA, nA);
        scan_step4(bB, nB, v, cac);
        t0 -= 4;
        if (t0 >= 11) scan_load4(kn, nr, t0 - 8, lane, bB, nB);
        scan_step4(bC, nC, v, cac);
        t0 -= 4;
    }

    // remainder: t = 2, 1, 0 single steps
    for (int t = 2; t >= 0; --t) {
        float kt[8];
        const float4* p = reinterpret_cast<const float4*>(kn + (size_t)t * STRD + lane * 8);
        float4 u = __ldg(p), w = __ldg(p + 1);
        kt[0] = u.x; kt[1] = u.y; kt[2] = u.z; kt[3] = u.w;
        kt[4] = w.x; kt[5] = w.y; kt[6] = w.z; kt[7] = w.w;
        float nt = __ldg(nr + (size_t)t * B);
        float s = 0.f;
#pragma unroll
        for (int j = 0; j < 8; ++j) s += kt[j] * v[j];
#pragma unroll
        for (int off = 16; off > 0; off >>= 1) s += __shfl_xor_sync(0xffffffffu, s, off);
        float ws = nt * s;
#pragma unroll
        for (int j = 0; j < 8; ++j) {
            cac[j] += kt[j] * ws;
            v[j] -= ALPHA_C * s * kt[j];
        }
    }

    float* out = cbuf + b * H + m * HALF + lane * 8;
#pragma unroll
    for (int j = 0; j < 8; ++j) out[j] = ALPHA_C * cac[j];
}

// ---------------- r = c @ rp_w^T + rp_b ----------------
__global__ void k_rp(const float* __restrict__ c, const float* __restrict__ W,
                     const float* __restrict__ bias, float* __restrict__ r) {
    __shared__ float cs[B * (H + 1)];
    for (int i = threadIdx.x; i < B * H; i += 256) {
        int bb = i >> 9, hh = i & 511;
        cs[bb * (H + 1) + hh] = c[i];
    }
    __syncthreads();
    int g = blockIdx.x * 16 + (threadIdx.x >> 4);
    int b = threadIdx.x & 15;
    const float* w = W + (size_t)g * H;
    const float* cb = &cs[b * (H + 1)];
    float acc = 0.f;
    for (int h = 0; h < H; h += 4) {
        float4 wv = __ldg(reinterpret_cast<const float4*>(w + h));
        acc += cb[h] * wv.x + cb[h + 1] * wv.y + cb[h + 2] * wv.z + cb[h + 3] * wv.w;
    }
    r[b * H + g] = acc + bias[g];
}

// ---------------- out = r @ out_w^T + out_b ----------------
__global__ void k_out(const float* __restrict__ r, const float* __restrict__ W,
                      const float* __restrict__ bias, float* __restrict__ out) {
    __shared__ float rs[B * H];
    for (int i = threadIdx.x; i < B * H; i += 256) rs[i] = r[i];
    __syncthreads();
    int v = blockIdx.x * 256 + threadIdx.x;
    float acc[B];
#pragma unroll
    for (int b = 0; b < B; ++b) acc[b] = 0.f;
    const float4* w = reinterpret_cast<const float4*>(W + (size_t)v * H);
#pragma unroll 4
    for (int i = 0; i < H / 4; ++i) {
        float4 wv = __ldg(w + i);
#pragma unroll
        for (int b = 0; b < B; ++b) {
            float4 rv = *reinterpret_cast<const float4*>(&rs[b * H + i * 4]);
            acc[b] += rv.x * wv.x + rv.y * wv.y + rv.z * wv.z + rv.w * wv.w;
        }
    }
    float bb = __ldg(bias + v);
#pragma unroll
    for (int b = 0; b < B; ++b) out[(size_t)b * V + v] = acc[b] + bb;
}

// ---------------- launch ----------------
extern "C" void kernel_launch(void* const* d_in, const int* in_sizes, int n_in,
                              void* d_out, int out_size) {
    const int*   seq   = (const int*)d_in[0];
    const float* embed = (const float*)d_in[1];
    const float* ff_w1 = (const float*)d_in[2];
    const float* ff_b1 = (const float*)d_in[3];
    const float* ff_w2 = (const float*)d_in[4];
    const float* ff_b2 = (const float*)d_in[5];
    const float* gamma = (const float*)d_in[6];
    const float* beta  = (const float*)d_in[7];
    const float* sem_w = (const float*)d_in[8];
    const float* epi_w = (const float*)d_in[9];
    const float* rp_w  = (const float*)d_in[10];
    const float* rp_b  = (const float*)d_in[11];
    const float* out_w = (const float*)d_in[12];
    const float* out_b = (const float*)d_in[13];
    float* out = (float*)d_out;

    float *h0, *ff1, *y2, *h, *kn, *nrm, *c, *r, *w1r, *w2r, *semr, *epir;
    cudaGetSymbolAddress((void**)&h0,   g_h0);
    cudaGetSymbolAddress((void**)&ff1,  g_ff1);
    cudaGetSymbolAddress((void**)&y2,   g_y2);
    cudaGetSymbolAddress((void**)&h,    g_h);
    cudaGetSymbolAddress((void**)&kn,   g_kn);
    cudaGetSymbolAddress((void**)&nrm,  g_nrm);
    cudaGetSymbolAddress((void**)&c,    g_c);
    cudaGetSymbolAddress((void**)&r,    g_r);
    cudaGetSymbolAddress((void**)&w1r,  g_w1r);
    cudaGetSymbolAddress((void**)&w2r,  g_w2r);
    cudaGetSymbolAddress((void**)&semr, g_semr);
    cudaGetSymbolAddress((void**)&epir, g_epir);

    // 0. pre-round weights to tf32
    k_round<<<(2 * H * H) / 1024, 256>>>(ff_w1, w1r);
    k_round<<<(2 * H * H) / 1024, 256>>>(ff_w2, w2r);
    k_round<<<(HALF * H) / 1024, 256>>>(sem_w, semr);
    k_round<<<(HALF * H) / 1024, 256>>>(epi_w, epir);
    // 1. embedding gather (rounds)
    k_gather<<<TOK, 128>>>(seq, embed, h0);
    // 2. FFN up (relu, rounds)   [16384 x 1024 x 512]
    k_gemm<1><<<dim3(2 * H / 128, TOK / 128), 256>>>(h0, w1r, ff_b1, ff1, 2 * H, H);
    // 3. FFN down        [16384 x 512 x 1024]
    k_gemm<0><<<dim3(H / 128, TOK / 128), 256>>>(ff1, w2r, ff_b2, y2, H, 2 * H);
    // 4. residual + layernorm (rounds)
    k_ln<<<TOK / 8, 256>>>(y2, h0, gamma, beta, h);
    // 5+6. key projections, scattered to [l][b][c]
    k_gemm<2><<<dim3(HALF / 128, TOK / 128), 256>>>(h, semr, nullptr, kn, HALF, H);
    k_gemm<2><<<dim3(HALF / 128, TOK / 128), 256>>>(h, epir, nullptr,
                                                    kn + (size_t)L * B * HALF, HALF, H);
    // 7. normalize keys in place, stash clamped norms
    k_norm<<<(2 * L * B) / 8, 256>>>(kn, nrm);
    // 8. backward-query scan (prefetch-2)
    k_scan<<<32, 32>>>(kn, nrm, c);
    // 9. readout projection
    k_rp<<<H / 16, 256>>>(c, rp_w, rp_b, r);
    // 10. logits
    k_out<<<V / 256, 256>>>(r, out_w, out_b, out);
}

// round 7
// speedup vs baseline: 1.8761x; 1.3650x over previous
#include <cuda_runtime.h>
#include <cuda_fp16.h>
#include <cstdint>

namespace {
constexpr int B = 16;
constexpr int L = 1024;
constexpr int H = 512;
constexpr int V = 32000;
constexpr int HALF = 256;
constexpr int TOK = B * L;           // 16384
constexpr float ALPHA_C = 0.05f;     // 1 - 0.95
constexpr float EPS_LN_C = 1e-5f;
constexpr float EPS_NORM_C = 1e-12f;

// GEMM tiling (fp16 operands, fp32 accum)
constexpr int TM = 128;
constexpr int TN = 128;
constexpr int TKH = 64;              // halves per k-tile = 128 bytes per row
constexpr int STG = 3;               // cp.async stages
constexpr int TILE_BYTES = 128 * 128;            // 16 KB per matrix per stage
constexpr int SMEM_H = STG * 2 * TILE_BYTES;     // 96 KB
}

// ---------------- scratch (static device globals; no allocation) ----------------
__device__ __half g_h0h[TOK * H];            // embed gather output (fp16)
__device__ __half g_ff1h[TOK * 2 * H];       // FFN hidden (fp16)
__device__ float  g_y2[TOK * H];             // FFN output (pre-LN, fp32)
__device__ __half g_hh[TOK * H];             // post-LN hidden (fp16)
__device__ float  g_kn[2 * L * B * HALF];    // normalized keys [m][l][b][i]
__device__ float  g_nrm[2 * L * B];          // clamped norms [m][l][b]
__device__ float  g_c[B * H];                // context
__device__ float  g_r[B * H];                // readout projection
__device__ __half g_w1h[2 * H * H];          // fp16 ff_w1
__device__ __half g_w2h[2 * H * H];          // fp16 ff_w2
__device__ __half g_wch[2 * HALF * H];       // fp16 [sem_w ; epi_w]

// ---------------- helpers ----------------
__device__ __forceinline__ uint32_t smem_u32(const void* p) {
    return (uint32_t)__cvta_generic_to_shared(p);
}
__device__ __forceinline__ void cp16(uint32_t dst, const void* src) {
    asm volatile("cp.async.cg.shared.global [%0], [%1], 16;" :: "r"(dst), "l"(src));
}
__device__ __forceinline__ uint32_t sw128(uint32_t off) {
    return off ^ ((off >> 3) & 0x70u);
}
__device__ __forceinline__ void ldsm_x4(uint32_t& r0, uint32_t& r1, uint32_t& r2,
                                        uint32_t& r3, uint32_t a) {
    asm volatile("ldmatrix.sync.aligned.m8n8.x4.shared.b16 {%0,%1,%2,%3}, [%4];"
                 : "=r"(r0), "=r"(r1), "=r"(r2), "=r"(r3) : "r"(a));
}
__device__ __forceinline__ void ldsm_x2(uint32_t& r0, uint32_t& r1, uint32_t a) {
    asm volatile("ldmatrix.sync.aligned.m8n8.x2.shared.b16 {%0,%1}, [%2];"
                 : "=r"(r0), "=r"(r1) : "r"(a));
}
__device__ __forceinline__ void mma_f16(float* d, const uint32_t* a, const uint32_t* b) {
    asm volatile(
        "mma.sync.aligned.m16n8k16.row.col.f32.f16.f16.f32 "
        "{%0,%1,%2,%3},{%4,%5,%6,%7},{%8,%9},{%0,%1,%2,%3};"
        : "+f"(d[0]), "+f"(d[1]), "+f"(d[2]), "+f"(d[3])
        : "r"(a[0]), "r"(a[1]), "r"(a[2]), "r"(a[3]), "r"(b[0]), "r"(b[1]));
}

// ---------------- fp32 -> fp16 weight conversion ----------------
__global__ void k_round(const float* __restrict__ src, __half* __restrict__ dst) {
    int i = blockIdx.x * 256 + threadIdx.x;       // 4 floats per thread
    float4 v = __ldg(reinterpret_cast<const float4*>(src) + i);
    __half2* d = reinterpret_cast<__half2*>(dst) + i * 2;
    d[0] = __floats2half2_rn(v.x, v.y);
    d[1] = __floats2half2_rn(v.z, v.w);
}

// ---------------- embedding gather (fp16 out) ----------------
__global__ void k_gather(const int* __restrict__ seq, const float* __restrict__ embed,
                         __half* __restrict__ out) {
    int t = blockIdx.x;
    int v = seq[t];
    const float4* src = reinterpret_cast<const float4*>(embed + (size_t)v * H);
    float4 x = src[threadIdx.x];
    __half2* dst = reinterpret_cast<__half2*>(out + (size_t)t * H) + threadIdx.x * 2;
    dst[0] = __floats2half2_rn(x.x, x.y);
    dst[1] = __floats2half2_rn(x.z, x.w);
}

// ---------------- fp16 tensor GEMM: C[m,n] = A[m,:] . W[n,:] ----------------
// A [M,K], W [N,K] fp16 row-major. 128x128 CTA tile, BK=64 halves (128B rows,
// SW128), 3-stage cp.async, 8 warps in 2x4 grid, 64x32 warp tiles, fp32 accum.
// MODE 0: +bias -> fp32 C;  MODE 1: +bias+relu -> fp16 C;
// MODE 2: no bias, scatter fp32 to kn[m][l][b][c] (N=512 = two m-halves)
template <int MODE>
__global__ void __launch_bounds__(256) k_gemm(const __half* __restrict__ A,
                                              const __half* __restrict__ W,
                                              const float* __restrict__ bias,
                                              void* __restrict__ Cv,
                                              int N, int K) {
    extern __shared__ char smem[];
    const uint32_t sb = smem_u32(smem);
    uint32_t a_off[STG], w_off[STG];
#pragma unroll
    for (int s = 0; s < STG; ++s) {
        a_off[s] = s * 2 * TILE_BYTES;
        w_off[s] = s * 2 * TILE_BYTES + TILE_BYTES;
    }

    const int tid = threadIdx.x;
    const int bm = blockIdx.y * TM;
    const int bn = blockIdx.x * TN;
    const int warp = tid >> 5, lane = tid & 31;
    const int wm = warp >> 2, wn = warp & 3;   // 2 x 4 warp grid
    const int g = lane >> 2, tg = lane & 3;

    // global loader: 256 threads cover 128 rows x 128B per matrix (4 x 16B each)
    const int row = tid >> 1;
    const int h64 = tid & 1;
    const __half* Ag = A + (size_t)(bm + row) * K + h64 * 32;
    const __half* Wg = W + (size_t)(bn + row) * K + h64 * 32;
    uint32_t swz[4];
#pragma unroll
    for (int c = 0; c < 4; ++c) swz[c] = sw128(row * 128 + h64 * 64 + c * 16);

    float acc[4][4][4];
#pragma unroll
    for (int mi = 0; mi < 4; ++mi)
#pragma unroll
        for (int ni = 0; ni < 4; ++ni)
#pragma unroll
            for (int q = 0; q < 4; ++q) acc[mi][ni][q] = 0.f;

    auto issue_tile = [&](int st, int kt) {
#pragma unroll
        for (int c = 0; c < 4; ++c)
            cp16(sb + a_off[st] + swz[c], Ag + (size_t)kt * TKH + c * 8);
#pragma unroll
        for (int c = 0; c < 4; ++c)
            cp16(sb + w_off[st] + swz[c], Wg + (size_t)kt * TKH + c * 8);
        asm volatile("cp.async.commit_group;" ::: "memory");
    };

    // ldsm lane addressing within a tile
    const int a_r = lane & 15;
    const int a_cb = (lane >> 4) * 16;        // byte offset of k-half
    const int b_r = lane & 7;
    const int b_cb = ((lane >> 3) & 1) * 16;

    auto mma_pass = [&](int buf) {
#pragma unroll
        for (int ak = 0; ak < 4; ++ak) {
            const int kb = ak * 32;           // 16 halves = 32 bytes per ak step
            uint32_t afrag[4][4];
#pragma unroll
            for (int mi = 0; mi < 4; ++mi) {
                uint32_t addr = sb + a_off[buf] +
                    sw128((uint32_t)(wm * 64 + mi * 16 + a_r) * 128 + kb + a_cb);
                ldsm_x4(afrag[mi][0], afrag[mi][1], afrag[mi][2], afrag[mi][3], addr);
            }
            uint32_t bfrag[4][2];
#pragma unroll
            for (int ni = 0; ni < 4; ++ni) {
                uint32_t addr = sb + w_off[buf] +
                    sw128((uint32_t)(wn * 32 + ni * 8 + b_r) * 128 + kb + b_cb);
                ldsm_x2(bfrag[ni][0], bfrag[ni][1], addr);
            }
#pragma unroll
            for (int mi = 0; mi < 4; ++mi)
#pragma unroll
                for (int ni = 0; ni < 4; ++ni)
                    mma_f16(acc[mi][ni], afrag[mi], bfrag[ni]);
        }
    };

    const int NPASS = K / TKH;
    issue_tile(0, 0);
    issue_tile(1, 1);

    int p = 0;
    for (; p < NPASS - 1; ++p) {
        asm volatile("cp.async.wait_group 1;" ::: "memory");
        __syncthreads();
        if (p + 2 < NPASS) issue_tile((p + 2) % STG, p + 2);
        mma_pass(p % STG);
    }
    asm volatile("cp.async.wait_group 0;" ::: "memory");
    __syncthreads();
    mma_pass(p % STG);

    // epilogue: acc reg q -> row g + (q>=2)*8, col tg*2 + (q&1)
#pragma unroll
    for (int mi = 0; mi < 4; ++mi) {
#pragma unroll
        for (int half = 0; half < 2; ++half) {
            int r = bm + wm * 64 + mi * 16 + g + half * 8;
#pragma unroll
            for (int ni = 0; ni < 4; ++ni) {
                int col = bn + wn * 32 + ni * 8 + tg * 2;
                float x = acc[mi][ni][half * 2 + 0];
                float y = acc[mi][ni][half * 2 + 1];
                if (MODE == 2) {
                    int b_ = r >> 10, l_ = r & 1023;
                    int m_ = col >> 8, c_ = col & 255;
                    float* dst = (float*)Cv + (size_t)m_ * (L * B * HALF) +
                                 ((size_t)l_ * B + b_) * HALF + c_;
                    *reinterpret_cast<float2*>(dst) = make_float2(x, y);
                } else if (MODE == 0) {
                    x += bias[col];
                    y += bias[col + 1];
                    float* dst = (float*)Cv + (size_t)r * N + col;
                    *reinterpret_cast<float2*>(dst) = make_float2(x, y);
                } else {
                    x = fmaxf(x + bias[col], 0.f);
                    y = fmaxf(y + bias[col + 1], 0.f);
                    __half* dst = (__half*)Cv + (size_t)r * N + col;
                    *reinterpret_cast<__half2*>(dst) = __floats2half2_rn(x, y);
                }
            }
        }
    }
}

// ---------------- residual + LayerNorm (warp per row; fp16 out) ----------------
__global__ void k_ln(const float* __restrict__ y2, const __half* __restrict__ h0,
                     const float* __restrict__ gamma, const float* __restrict__ beta,
                     __half* __restrict__ out) {
    int warp = threadIdx.x >> 5, lane = threadIdx.x & 31;
    int row = blockIdx.x * 8 + warp;
    const float4* a = reinterpret_cast<const float4*>(y2 + (size_t)row * H);
    const __half2* hb = reinterpret_cast<const __half2*>(h0 + (size_t)row * H);
    float x[16];
    float s = 0.f, s2 = 0.f;
#pragma unroll
    for (int i = 0; i < 4; ++i) {
        float4 u = a[lane + i * 32];
        float2 v0 = __half22float2(hb[(lane + i * 32) * 2]);
        float2 v1 = __half22float2(hb[(lane + i * 32) * 2 + 1]);
        float t0 = u.x + v0.x, t1 = u.y + v0.y, t2 = u.z + v1.x, t3 = u.w + v1.y;
        x[i * 4 + 0] = t0; x[i * 4 + 1] = t1; x[i * 4 + 2] = t2; x[i * 4 + 3] = t3;
        s += t0 + t1 + t2 + t3;
        s2 += t0 * t0 + t1 * t1 + t2 * t2 + t3 * t3;
    }
#pragma unroll
    for (int off = 16; off > 0; off >>= 1) {
        s += __shfl_xor_sync(0xffffffffu, s, off);
        s2 += __shfl_xor_sync(0xffffffffu, s2, off);
    }
    float mu = s * (1.f / H);
    float var = s2 * (1.f / H) - mu * mu;
    float rstd = rsqrtf(var + EPS_LN_C);
    __half2* o = reinterpret_cast<__half2*>(out + (size_t)row * H);
    const float4* g4 = reinterpret_cast<const float4*>(gamma);
    const float4* b4 = reinterpret_cast<const float4*>(beta);
#pragma unroll
    for (int i = 0; i < 4; ++i) {
        float4 gg = __ldg(g4 + lane + i * 32);
        float4 bb = __ldg(b4 + lane + i * 32);
        float r0 = (x[i * 4 + 0] - mu) * rstd * gg.x + bb.x;
        float r1 = (x[i * 4 + 1] - mu) * rstd * gg.y + bb.y;
        float r2 = (x[i * 4 + 2] - mu) * rstd * gg.z + bb.z;
        float r3 = (x[i * 4 + 3] - mu) * rstd * gg.w + bb.w;
        o[(lane + i * 32) * 2] = __floats2half2_rn(r0, r1);
        o[(lane + i * 32) * 2 + 1] = __floats2half2_rn(r2, r3);
    }
}

// ---------------- L2-normalize key rows in place, save clamped norm ----------------
__global__ void k_norm(float* __restrict__ kn, float* __restrict__ nrm) {
    int warp = threadIdx.x >> 5, lane = threadIdx.x & 31;
    int row = blockIdx.x * 8 + warp;               // 0 .. 2*L*B-1
    float4* p4 = reinterpret_cast<float4*>(kn + (size_t)row * HALF);
    float4 v0 = p4[lane];
    float4 v1 = p4[lane + 32];
    float s = v0.x * v0.x + v0.y * v0.y + v0.z * v0.z + v0.w * v0.w
            + v1.x * v1.x + v1.y * v1.y + v1.z * v1.z + v1.w * v1.w;
#pragma unroll
    for (int off = 16; off > 0; off >>= 1) s += __shfl_xor_sync(0xffffffffu, s, off);
    float n = sqrtf(s);
    float nc = fmaxf(n, EPS_NORM_C);
    float inv = 1.f / nc;
    v0.x *= inv; v0.y *= inv; v0.z *= inv; v0.w *= inv;
    v1.x *= inv; v1.y *= inv; v1.z *= inv; v1.w *= inv;
    p4[lane] = v0;
    p4[lane + 32] = v1;
    if (lane == 0) nrm[row] = nc;
}

// ---------------- EMA scan, backward-query form, prefetch distance 2 ----------------
__device__ __forceinline__ void scan_load4(const float* kn, const float* nr, int t0,
                                           int lane, float k4[4][8], float n4[4]) {
    const int STRD = B * HALF;
#pragma unroll
    for (int j = 0; j < 4; ++j) {
        const float4* p = reinterpret_cast<const float4*>(kn + (size_t)(t0 + j) * STRD + lane * 8);
        float4 u = __ldg(p), w = __ldg(p + 1);
        k4[j][0] = u.x; k4[j][1] = u.y; k4[j][2] = u.z; k4[j][3] = u.w;
        k4[j][4] = w.x; k4[j][5] = w.y; k4[j][6] = w.z; k4[j][7] = w.w;
        n4[j] = __ldg(nr + (size_t)(t0 + j) * B);
    }
}

__device__ __forceinline__ void scan_step4(const float cur[4][8], const float curn[4],
                                           float v[8], float cac[8]) {
    float red[10];
#pragma unroll
    for (int q = 0; q < 10; ++q) red[q] = 0.f;
#pragma unroll
    for (int j = 0; j < 8; ++j) {
        float vj = v[j];
        float k0 = cur[0][j], k1 = cur[1][j], k2 = cur[2][j], k3 = cur[3][j];
        red[0] += k0 * vj;
        red[1] += k1 * vj;
        red[2] += k2 * vj;
        red[3] += k3 * vj;
        red[4] += k3 * k2;
        red[5] += k3 * k1;
        red[6] += k3 * k0;
        red[7] += k2 * k1;
        red[8] += k2 * k0;
        red[9] += k1 * k0;
    }
#pragma unroll
    for (int off = 16; off > 0; off >>= 1)
#pragma unroll
        for (int q = 0; q < 10; ++q)
            red[q] += __shfl_xor_sync(0xffffffffu, red[q], off);

    float s3 = red[3];
    float s2 = red[2] - ALPHA_C * red[4] * s3;
    float s1 = red[1] - ALPHA_C * (red[5] * s3 + red[7] * s2);
    float s0 = red[0] - ALPHA_C * (red[6] * s3 + red[8] * s2 + red[9] * s1);
    float w3 = curn[3] * s3, w2 = curn[2] * s2, w1 = curn[1] * s1, w0 = curn[0] * s0;
#pragma unroll
    for (int j = 0; j < 8; ++j) {
        float k0 = cur[0][j], k1 = cur[1][j], k2 = cur[2][j], k3 = cur[3][j];
        v[j] -= ALPHA_C * (k3 * s3 + k2 * s2 + k1 * s1 + k0 * s0);
        cac[j] += k3 * w3 + k2 * w2 + k1 * w1 + k0 * w0;
    }
}

__global__ void __launch_bounds__(32) k_scan(const float* __restrict__ kn_all,
                                             const float* __restrict__ nrm_all,
                                             float* __restrict__ cbuf) {
    const int lane = threadIdx.x;
    const int m = blockIdx.x >> 4;
    const int b = blockIdx.x & 15;
    const float* kn = kn_all + (size_t)m * L * B * HALF + b * HALF;
    const float* nr = nrm_all + (size_t)m * L * B + b;
    const int STRD = B * HALF;

    float v[8], cac[8];
    {
        const float4* p = reinterpret_cast<const float4*>(kn + (size_t)(L - 1) * STRD + lane * 8);
        float4 u = __ldg(p), w = __ldg(p + 1);
        float qn = __ldg(nr + (size_t)(L - 1) * B);
        v[0] = u.x * qn; v[1] = u.y * qn; v[2] = u.z * qn; v[3] = u.w * qn;
        v[4] = w.x * qn; v[5] = w.y * qn; v[6] = w.z * qn; v[7] = w.w * qn;
    }
#pragma unroll
    for (int j = 0; j < 8; ++j) cac[j] = 0.f;

    float bA[4][8], bB[4][8], bC[4][8], nA[4], nB[4], nC[4];
    scan_load4(kn, nr, L - 5, lane, bA, nA);    // t0 = 1019
    scan_load4(kn, nr, L - 9, lane, bB, nB);    // t0 = 1015

    int t0 = L - 5;
    for (int it = 0; it < 85; ++it) {
        if (t0 >= 11) scan_load4(kn, nr, t0 - 8, lane, bC, nC);
        scan_step4(bA, nA, v, cac);
        t0 -= 4;
        if (t0 >= 11) scan_load4(kn, nr, t0 - 8, lane, bA, nA);
        scan_step4(bB, nB, v, cac);
        t0 -= 4;
        if (t0 >= 11) scan_load4(kn, nr, t0 - 8, lane, bB, nB);
        scan_step4(bC, nC, v, cac);
        t0 -= 4;
    }

    // remainder: t = 2, 1, 0 single steps
    for (int t = 2; t >= 0; --t) {
        float kt[8];
        const float4* p = reinterpret_cast<const float4*>(kn + (size_t)t * STRD + lane * 8);
        float4 u = __ldg(p), w = __ldg(p + 1);
        kt[0] = u.x; kt[1] = u.y; kt[2] = u.z; kt[3] = u.w;
        kt[4] = w.x; kt[5] = w.y; kt[6] = w.z; kt[7] = w.w;
        float nt = __ldg(nr + (size_t)t * B);
        float s = 0.f;
#pragma unroll
        for (int j = 0; j < 8; ++j) s += kt[j] * v[j];
#pragma unroll
        for (int off = 16; off > 0; off >>= 1) s += __shfl_xor_sync(0xffffffffu, s, off);
        float ws = nt * s;
#pragma unroll
        for (int j = 0; j < 8; ++j) {
            cac[j] += kt[j] * ws;
            v[j] -= ALPHA_C * s * kt[j];
        }
    }

    float* out = cbuf + b * H + m * HALF + lane * 8;
#pragma unroll
    for (int j = 0; j < 8; ++j) out[j] = ALPHA_C * cac[j];
}

// ---------------- r = c @ rp_w^T + rp_b ----------------
__global__ void k_rp(const float* __restrict__ c, const float* __restrict__ W,
                     const float* __restrict__ bias, float* __restrict__ r) {
    __shared__ float cs[B * (H + 1)];
    for (int i = threadIdx.x; i < B * H; i += 256) {
        int bb = i >> 9, hh = i & 511;
        cs[bb * (H + 1) + hh] = c[i];
    }
    __syncthreads();
    int g = blockIdx.x * 16 + (threadIdx.x >> 4);
    int b = threadIdx.x & 15;
    const float* w = W + (size_t)g * H;
    const float* cb = &cs[b * (H + 1)];
    float acc = 0.f;
    for (int h = 0; h < H; h += 4) {
        float4 wv = __ldg(reinterpret_cast<const float4*>(w + h));
        acc += cb[h] * wv.x + cb[h + 1] * wv.y + cb[h + 2] * wv.z + cb[h + 3] * wv.w;
    }
    r[b * H + g] = acc + bias[g];
}

// ---------------- out = r @ out_w^T + out_b ----------------
__global__ void k_out(const float* __restrict__ r, const float* __restrict__ W,
                      const float* __restrict__ bias, float* __restrict__ out) {
    __shared__ float rs[B * H];
    for (int i = threadIdx.x; i < B * H; i += 256) rs[i] = r[i];
    __syncthreads();
    int v = blockIdx.x * 256 + threadIdx.x;
    float acc[B];
#pragma unroll
    for (int b = 0; b < B; ++b) acc[b] = 0.f;
    const float4* w = reinterpret_cast<const float4*>(W + (size_t)v * H);
#pragma unroll 4
    for (int i = 0; i < H / 4; ++i) {
        float4 wv = __ldg(w + i);
#pragma unroll
        for (int b = 0; b < B; ++b) {
            float4 rv = *reinterpret_cast<const float4*>(&rs[b * H + i * 4]);
            acc[b] += rv.x * wv.x + rv.y * wv.y + rv.z * wv.z + rv.w * wv.w;
        }
    }
    float bb = __ldg(bias + v);
#pragma unroll
    for (int b = 0; b < B; ++b) out[(size_t)b * V + v] = acc[b] + bb;
}

// ---------------- launch ----------------
extern "C" void kernel_launch(void* const* d_in, const int* in_sizes, int n_in,
                              void* d_out, int out_size) {
    const int*   seq   = (const int*)d_in[0];
    const float* embed = (const float*)d_in[1];
    const float* ff_w1 = (const float*)d_in[2];
    const float* ff_b1 = (const float*)d_in[3];
    const float* ff_w2 = (const float*)d_in[4];
    const float* ff_b2 = (const float*)d_in[5];
    const float* gamma = (const float*)d_in[6];
    const float* beta  = (const float*)d_in[7];
    const float* sem_w = (const float*)d_in[8];
    const float* epi_w = (const float*)d_in[9];
    const float* rp_w  = (const float*)d_in[10];
    const float* rp_b  = (const float*)d_in[11];
    const float* out_w = (const float*)d_in[12];
    const float* out_b = (const float*)d_in[13];
    float* out = (float*)d_out;

    __half *h0h, *ff1h, *hh, *w1h, *w2h, *wch;
    float *y2, *kn, *nrm, *c, *r;
    cudaGetSymbolAddress((void**)&h0h,  g_h0h);
    cudaGetSymbolAddress((void**)&ff1h, g_ff1h);
    cudaGetSymbolAddress((void**)&y2,   g_y2);
    cudaGetSymbolAddress((void**)&hh,   g_hh);
    cudaGetSymbolAddress((void**)&kn,   g_kn);
    cudaGetSymbolAddress((void**)&nrm,  g_nrm);
    cudaGetSymbolAddress((void**)&c,    g_c);
    cudaGetSymbolAddress((void**)&r,    g_r);
    cudaGetSymbolAddress((void**)&w1h,  g_w1h);
    cudaGetSymbolAddress((void**)&w2h,  g_w2h);
    cudaGetSymbolAddress((void**)&wch,  g_wch);

    cudaFuncSetAttribute(k_gemm<0>, cudaFuncAttributeMaxDynamicSharedMemorySize, SMEM_H);
    cudaFuncSetAttribute(k_gemm<1>, cudaFuncAttributeMaxDynamicSharedMemorySize, SMEM_H);
    cudaFuncSetAttribute(k_gemm<2>, cudaFuncAttributeMaxDynamicSharedMemorySize, SMEM_H);

    // 0. convert weights to fp16 (keyproj weights concatenated)
    k_round<<<(2 * H * H) / 1024, 256>>>(ff_w1, w1h);
    k_round<<<(2 * H * H) / 1024, 256>>>(ff_w2, w2h);
    k_round<<<(HALF * H) / 1024, 256>>>(sem_w, wch);
    k_round<<<(HALF * H) / 1024, 256>>>(epi_w, wch + (size_t)HALF * H);
    // 1. embedding gather (fp16)
    k_gather<<<TOK, 128>>>(seq, embed, h0h);
    // 2. FFN up (relu, fp16 out)   [16384 x 1024 x 512]
    k_gemm<1><<<dim3(2 * H / TN, TOK / TM), 256, SMEM_H>>>(h0h, w1h, ff_b1, ff1h, 2 * H, H);
    // 3. FFN down (fp32 out)       [16384 x 512 x 1024]
    k_gemm<0><<<dim3(H / TN, TOK / TM), 256, SMEM_H>>>(ff1h, w2h, ff_b2, y2, H, 2 * H);
    // 4. residual + layernorm (fp16 out)
    k_ln<<<TOK / 8, 256>>>(y2, h0h, gamma, beta, hh);
    // 5. merged key projections (N=512), scattered to kn[m][l][b][c]
    k_gemm<2><<<dim3(2 * HALF / TN, TOK / TM), 256, SMEM_H>>>(hh, wch, nullptr, kn, 2 * HALF, H);
    // 6. normalize keys in place, stash clamped norms
    k_norm<<<(2 * L * B) / 8, 256>>>(kn, nrm);
    // 7. backward-query scan (prefetch-2)
    k_scan<<<32, 32>>>(kn, nrm, c);
    // 8. readout projection
    k_rp<<<H / 16, 256>>>(c, rp_w, rp_b, r);
    // 9. logits
    k_out<<<V / 256, 256>>>(r, out_w, out_b, out);
}